// round 8
// baseline (speedup 1.0000x reference)
#include <cuda_runtime.h>

#define HH 256
#define WW 256
#define HW 65536
#define BS 8
#define IC 16
#define OC 32
#define NSTEPS 7

typedef unsigned long long u64;

// Scratch (static device globals — no runtime allocation).
__device__ __align__(16) float  g_raw[BS * OC * HW];   // conv output (planar)
__device__ __align__(16) float2 g_fA[BS * IC * HW];    // interleaved flow ping
__device__ __align__(16) float2 g_fB[BS * IC * HW];    // interleaved flow pong
__device__ float g_part[2][OC][2048];                  // per-block partial (sum, sumsq)
__device__ float g_affa[OC];                           // BN affine scale (incl. 1/128)
__device__ float g_affb[OC];                           // BN affine shift (incl. 1/128)

__device__ __forceinline__ u64 pack2(float lo, float hi) {
    u64 r; asm("mov.b64 %0, {%1, %2};" : "=l"(r) : "f"(lo), "f"(hi)); return r;
}
__device__ __forceinline__ void unpack2(u64 v, float& lo, float& hi) {
    asm("mov.b64 {%0, %1}, %2;" : "=f"(lo), "=f"(hi) : "l"(v));
}
__device__ __forceinline__ u64 ffma2(u64 a, u64 b, u64 c) {
    u64 d; asm("fma.rn.f32x2 %0, %1, %2, %3;" : "=l"(d) : "l"(a), "l"(b), "l"(c)); return d;
}

// ---------------------------------------------------------------------------
// Conv 3x3 (16->32, pad 1) via packed f32x2 FMA + deterministic stats.
// Each thread: 4 oc x 8 px column strip; px pairs packed into f32x2.
// ---------------------------------------------------------------------------
__global__ __launch_bounds__(256) void conv_kernel(const float* __restrict__ f,
                                                   const float* __restrict__ vw,
                                                   const float* __restrict__ vb) {
    __shared__ float ft[IC * 10 * 34];
    __shared__ float ws[OC * 144];

    const int tid  = threadIdx.x;
    const int lane = tid & 31;
    const int wid  = tid >> 5;
    const int x0   = blockIdx.x * 32;
    const int y0   = blockIdx.y * 8;
    const int b    = blockIdx.z;

    for (int i = tid; i < OC * 144; i += 256) ws[i] = vw[i];

    const float* fb = f + (size_t)b * IC * HW;
    for (int i = tid; i < IC * 10 * 34; i += 256) {
        int ic = i / 340;
        int rem = i % 340;
        int r = rem / 34, cc = rem % 34;
        int yy = y0 - 1 + r, xx = x0 - 1 + cc;
        float v = 0.f;
        if (yy >= 0 && yy < HH && xx >= 0 && xx < WW) v = fb[ic * HW + yy * WW + xx];
        ft[i] = v;
    }
    __syncthreads();

    const int oc0 = wid * 4;
    u64 acc[4][4];   // 4 oc x 4 pixel-pairs (8 rows)
#pragma unroll
    for (int i = 0; i < 4; i++) {
        float bias = vb[oc0 + i];
        u64 bp = pack2(bias, bias);
#pragma unroll
        for (int j = 0; j < 4; j++) acc[i][j] = bp;
    }

    for (int ic = 0; ic < IC; ic++) {
        const float* ftc = ft + ic * 340;
#pragma unroll
        for (int kx = 0; kx < 3; kx++) {
            float col[10];
#pragma unroll
            for (int r = 0; r < 10; r++) col[r] = ftc[r * 34 + lane + kx];
            u64 colp[9];
#pragma unroll
            for (int r = 0; r < 9; r++) colp[r] = pack2(col[r], col[r + 1]);
#pragma unroll
            for (int i = 0; i < 4; i++) {
#pragma unroll
                for (int ky = 0; ky < 3; ky++) {
                    float w = ws[(oc0 + i) * 144 + ic * 9 + ky * 3 + kx];
                    u64 wd = pack2(w, w);
#pragma unroll
                    for (int j = 0; j < 4; j++)
                        acc[i][j] = ffma2(colp[2 * j + ky], wd, acc[i][j]);
                }
            }
        }
    }

    const int blk = (b * (int)gridDim.y + blockIdx.y) * (int)gridDim.x + blockIdx.x;
#pragma unroll
    for (int i = 0; i < 4; i++) {
        float s = 0.f, s2 = 0.f;
        float* dst = g_raw + (size_t)(b * OC + oc0 + i) * HW + y0 * WW + x0 + lane;
#pragma unroll
        for (int j = 0; j < 4; j++) {
            float v0, v1;
            unpack2(acc[i][j], v0, v1);
            dst[(2 * j) * WW] = v0;
            dst[(2 * j + 1) * WW] = v1;
            s += v0 + v1;
            s2 += v0 * v0 + v1 * v1;
        }
#pragma unroll
        for (int off = 16; off > 0; off >>= 1) {
            s  += __shfl_down_sync(0xffffffffu, s, off);
            s2 += __shfl_down_sync(0xffffffffu, s2, off);
        }
        if (lane == 0) {
            g_part[0][oc0 + i][blk] = s;
            g_part[1][oc0 + i][blk] = s2;
        }
    }
}

// ---------------------------------------------------------------------------
// Reduce partials -> BN affine, folded with 1/2^NSTEPS.
// ---------------------------------------------------------------------------
__global__ __launch_bounds__(256) void stats_kernel(const float* __restrict__ gamma,
                                                    const float* __restrict__ beta) {
    __shared__ float sm[256], sm2[256];
    const int ch = blockIdx.x, tid = threadIdx.x;
    float s = 0.f, s2 = 0.f;
    for (int i = tid; i < 2048; i += 256) {
        s += g_part[0][ch][i];
        s2 += g_part[1][ch][i];
    }
    sm[tid] = s; sm2[tid] = s2;
    __syncthreads();
    for (int off = 128; off > 0; off >>= 1) {
        if (tid < off) { sm[tid] += sm[tid + off]; sm2[tid] += sm2[tid + off]; }
        __syncthreads();
    }
    if (tid == 0) {
        const float n = (float)(BS * HW);
        float mean = sm[0] / n;
        float var = sm2[0] / n - mean * mean;
        float r = rsqrtf(var + 1e-5f);
        const float scale = 1.0f / 128.0f;
        g_affa[ch] = gamma[ch] * r * scale;
        g_affb[ch] = (beta[ch] - gamma[ch] * mean * r) * scale;
    }
}

// ---------------------------------------------------------------------------
// Bilinear gathers, zero-pad, shared base-index math (one base, +1/+256/+257,
// 4 bounds predicates).
// ---------------------------------------------------------------------------
__device__ __forceinline__ void gather_f2(const float2* __restrict__ pl,
                                          float py, float px,
                                          float& gy, float& gx) {
    float yf = floorf(py), xf = floorf(px);
    float wy1 = py - yf, wx1 = px - xf;
    float wy0 = 1.f - wy1, wx0 = 1.f - wx1;
    int yi = (int)yf, xi = (int)xf;
    bool y0v = (unsigned)yi < (unsigned)HH;
    bool y1v = (unsigned)(yi + 1) < (unsigned)HH;
    bool x0v = (unsigned)xi < (unsigned)WW;
    bool x1v = (unsigned)(xi + 1) < (unsigned)WW;
    int base = (yi << 8) + xi;
    float2 v00 = {0.f, 0.f}, v01 = {0.f, 0.f}, v10 = {0.f, 0.f}, v11 = {0.f, 0.f};
    if (y0v && x0v) v00 = pl[base];
    if (y0v && x1v) v01 = pl[base + 1];
    if (y1v && x0v) v10 = pl[base + 256];
    if (y1v && x1v) v11 = pl[base + 257];
    float w00 = wy0 * wx0, w01 = wy0 * wx1, w10 = wy1 * wx0, w11 = wy1 * wx1;
    gy = w00 * v00.x + w01 * v01.x + w10 * v10.x + w11 * v11.x;
    gx = w00 * v00.y + w01 * v01.y + w10 * v10.y + w11 * v11.y;
}

__device__ __forceinline__ float gather_f1(const float* __restrict__ pl,
                                           float py, float px) {
    float yf = floorf(py), xf = floorf(px);
    float wy1 = py - yf, wx1 = px - xf;
    float wy0 = 1.f - wy1, wx0 = 1.f - wx1;
    int yi = (int)yf, xi = (int)xf;
    bool y0v = (unsigned)yi < (unsigned)HH;
    bool y1v = (unsigned)(yi + 1) < (unsigned)HH;
    bool x0v = (unsigned)xi < (unsigned)WW;
    bool x1v = (unsigned)(xi + 1) < (unsigned)WW;
    int base = (yi << 8) + xi;
    float v00 = 0.f, v01 = 0.f, v10 = 0.f, v11 = 0.f;
    if (y0v && x0v) v00 = pl[base];
    if (y0v && x1v) v01 = pl[base + 1];
    if (y1v && x0v) v10 = pl[base + 256];
    if (y1v && x1v) v11 = pl[base + 257];
    return (wy0 * wx0) * v00 + (wy0 * wx1) * v01 + (wy1 * wx0) * v10 + (wy1 * wx1) * v11;
}

// ---------------------------------------------------------------------------
// One fused scaling-and-squaring step, two-phase block (512 thr, 32 px tile).
// Phase 1: thread (c, px) integrates flow, stores new flow, samples f -> smem.
// Phase 2: thread (o, px) mixes 16 smem samples with fuse weights, RMWs out.
// sm_m laid out [px][c] with pitch 20 -> conflict-free float4 loads in phase 2.
// LAST step skips the flow store (never read).
// ---------------------------------------------------------------------------
template <bool FIRST, bool LAST>
__global__ __launch_bounds__(512) void step_kernel(const float* __restrict__ f,
                                                   const float* __restrict__ fw,
                                                   const float* __restrict__ fbias,
                                                   float* __restrict__ out,
                                                   int step) {
    __shared__ __align__(16) float ws[256];       // [o][c]
    __shared__ float fb_s[16];
    __shared__ __align__(16) float sm_m[32][20];  // [px][c], pitch 20

    const int tid = threadIdx.x;
    if (tid < 256) {
        int o = tid >> 4, c = tid & 15;
        ws[o * 16 + c] = fw[(o * 16 + c) * NSTEPS + step];
    }
    if (tid < 16) fb_s[tid] = fbias[tid];

    const int pix0 = blockIdx.x * 32;
    const int b  = pix0 >> 16;
    const int p0 = pix0 & 65535;

    // ---------------- phase 1 ----------------
    {
        const int c  = tid >> 5;
        const int pj = tid & 31;
        const int p  = p0 + pj;
        const float fy = (float)(p >> 8), fx = (float)(p & 255);

        float ndy, ndx;
        if (FIRST) {
            const float* pdy = g_raw + (size_t)(b * OC + 2 * c) * HW;
            const float* pdx = pdy + HW;
            float a0 = g_affa[2 * c],     b0 = g_affb[2 * c];
            float a1 = g_affa[2 * c + 1], b1 = g_affb[2 * c + 1];
            float dy = fmaf(a0, pdy[p], b0);
            float dx = fmaf(a1, pdx[p], b1);
            float py = fy + dy, px = fx + dx;
            float yf = floorf(py), xf = floorf(px);
            float wy1 = py - yf, wx1 = px - xf;
            float wy0 = 1.f - wy1, wx0 = 1.f - wx1;
            int yi = (int)yf, xi = (int)xf;
            bool y0v = (unsigned)yi < (unsigned)HH;
            bool y1v = (unsigned)(yi + 1) < (unsigned)HH;
            bool x0v = (unsigned)xi < (unsigned)WW;
            bool x1v = (unsigned)(xi + 1) < (unsigned)WW;
            int base = (yi << 8) + xi;
            float wdy = 0.f, wdx = 0.f;
            float w00 = wy0 * wx0, w01 = wy0 * wx1, w10 = wy1 * wx0, w11 = wy1 * wx1;
            if (y0v && x0v) { wdy += w00 * fmaf(a0, pdy[base],       b0); wdx += w00 * fmaf(a1, pdx[base],       b1); }
            if (y0v && x1v) { wdy += w01 * fmaf(a0, pdy[base + 1],   b0); wdx += w01 * fmaf(a1, pdx[base + 1],   b1); }
            if (y1v && x0v) { wdy += w10 * fmaf(a0, pdy[base + 256], b0); wdx += w10 * fmaf(a1, pdx[base + 256], b1); }
            if (y1v && x1v) { wdy += w11 * fmaf(a0, pdy[base + 257], b0); wdx += w11 * fmaf(a1, pdx[base + 257], b1); }
            ndy = dy + wdy;
            ndx = dx + wdx;
        } else {
            const float2* pc = ((step & 1) ? g_fA : g_fB) + (size_t)(b * IC + c) * HW;
            float2 cv = pc[p];
            float dy = cv.x, dx = cv.y;
            float wdy, wdx;
            gather_f2(pc, fy + dy, fx + dx, wdy, wdx);
            ndy = dy + wdy;
            ndx = dx + wdx;
        }

        if (!LAST) {
            float2* vout = (FIRST ? g_fA : ((step & 1) ? g_fB : g_fA));
            float2 sv; sv.x = ndy; sv.y = ndx;
            vout[(size_t)(b * IC + c) * HW + p] = sv;
        }

        const float* fp = f + (size_t)(b * IC + c) * HW;
        sm_m[pj][c] = gather_f1(fp, fy + ndy, fx + ndx);
    }

    __syncthreads();

    // ---------------- phase 2 ----------------
    {
        const int o  = tid >> 5;
        const int pj = tid & 31;
        const int p  = p0 + pj;
        float* op = out + (size_t)(b * IC + o) * HW + p;

        float acc = FIRST ? fb_s[o] : *op;
        const float* wr = ws + o * 16;
#pragma unroll
        for (int g = 0; g < 4; g++) {
            float4 mv = *(const float4*)(&sm_m[pj][g * 4]);
            acc += wr[g * 4 + 0] * mv.x + wr[g * 4 + 1] * mv.y
                 + wr[g * 4 + 2] * mv.z + wr[g * 4 + 3] * mv.w;
        }
        *op = acc;
    }
}

extern "C" void kernel_launch(void* const* d_in, const int* in_sizes, int n_in,
                              void* d_out, int out_size) {
    const float* f     = (const float*)d_in[0];
    const float* vw    = (const float*)d_in[1];
    const float* vb    = (const float*)d_in[2];
    const float* gamma = (const float*)d_in[3];
    const float* beta  = (const float*)d_in[4];
    const float* fw    = (const float*)d_in[5];
    const float* fbias = (const float*)d_in[6];
    float* out = (float*)d_out;

    dim3 cg(8, 32, 8);
    conv_kernel<<<cg, 256>>>(f, vw, vb);
    stats_kernel<<<32, 256>>>(gamma, beta);
    const int nblk = BS * HW / 32;   // 16384
    // step 0 writes g_fA; step s>=1: odd reads g_fA->writes g_fB, even reads g_fB->writes g_fA
    step_kernel<true, false><<<nblk, 512>>>(f, fw, fbias, out, 0);
    for (int s = 1; s < NSTEPS - 1; s++)
        step_kernel<false, false><<<nblk, 512>>>(f, fw, fbias, out, s);
    step_kernel<false, true><<<nblk, 512>>>(f, fw, fbias, out, NSTEPS - 1);
}

// round 10
// speedup vs baseline: 1.1384x; 1.1384x over previous
#include <cuda_runtime.h>

#define HH 256
#define WW 256
#define HW 65536
#define BS 8
#define IC 16
#define OC 32
#define NSTEPS 7

typedef unsigned long long u64;

// Scratch (static device globals — no runtime allocation).
__device__ __align__(16) float  g_raw[BS * OC * HW];   // conv output (planar)
__device__ __align__(16) float2 g_fA[BS * IC * HW];    // interleaved flow ping
__device__ __align__(16) float2 g_fB[BS * IC * HW];    // interleaved flow pong
__device__ float g_part[2][OC][2048];                  // per-block partial (sum, sumsq)
__device__ float g_affa[OC];                           // BN affine scale (incl. 1/128)
__device__ float g_affb[OC];                           // BN affine shift (incl. 1/128)

__device__ __forceinline__ u64 pack2(float lo, float hi) {
    u64 r; asm("mov.b64 %0, {%1, %2};" : "=l"(r) : "f"(lo), "f"(hi)); return r;
}
__device__ __forceinline__ void unpack2(u64 v, float& lo, float& hi) {
    asm("mov.b64 {%0, %1}, %2;" : "=f"(lo), "=f"(hi) : "l"(v));
}
__device__ __forceinline__ u64 ffma2(u64 a, u64 b, u64 c) {
    u64 d; asm("fma.rn.f32x2 %0, %1, %2, %3;" : "=l"(d) : "l"(a), "l"(b), "l"(c)); return d;
}

// ---------------------------------------------------------------------------
// Conv 3x3 (16->32, pad 1) via packed f32x2 FMA + deterministic stats.
// ---------------------------------------------------------------------------
__global__ __launch_bounds__(256) void conv_kernel(const float* __restrict__ f,
                                                   const float* __restrict__ vw,
                                                   const float* __restrict__ vb) {
    __shared__ float ft[IC * 10 * 34];
    __shared__ float ws[OC * 144];

    const int tid  = threadIdx.x;
    const int lane = tid & 31;
    const int wid  = tid >> 5;
    const int x0   = blockIdx.x * 32;
    const int y0   = blockIdx.y * 8;
    const int b    = blockIdx.z;

    for (int i = tid; i < OC * 144; i += 256) ws[i] = vw[i];

    const float* fb = f + (size_t)b * IC * HW;
    for (int i = tid; i < IC * 10 * 34; i += 256) {
        int ic = i / 340;
        int rem = i % 340;
        int r = rem / 34, cc = rem % 34;
        int yy = y0 - 1 + r, xx = x0 - 1 + cc;
        float v = 0.f;
        if (yy >= 0 && yy < HH && xx >= 0 && xx < WW) v = fb[ic * HW + yy * WW + xx];
        ft[i] = v;
    }
    __syncthreads();

    const int oc0 = wid * 4;
    u64 acc[4][4];   // 4 oc x 4 pixel-pairs (8 rows)
#pragma unroll
    for (int i = 0; i < 4; i++) {
        float bias = vb[oc0 + i];
        u64 bp = pack2(bias, bias);
#pragma unroll
        for (int j = 0; j < 4; j++) acc[i][j] = bp;
    }

    for (int ic = 0; ic < IC; ic++) {
        const float* ftc = ft + ic * 340;
#pragma unroll
        for (int kx = 0; kx < 3; kx++) {
            float col[10];
#pragma unroll
            for (int r = 0; r < 10; r++) col[r] = ftc[r * 34 + lane + kx];
            u64 colp[9];
#pragma unroll
            for (int r = 0; r < 9; r++) colp[r] = pack2(col[r], col[r + 1]);
#pragma unroll
            for (int i = 0; i < 4; i++) {
#pragma unroll
                for (int ky = 0; ky < 3; ky++) {
                    float w = ws[(oc0 + i) * 144 + ic * 9 + ky * 3 + kx];
                    u64 wd = pack2(w, w);
#pragma unroll
                    for (int j = 0; j < 4; j++)
                        acc[i][j] = ffma2(colp[2 * j + ky], wd, acc[i][j]);
                }
            }
        }
    }

    const int blk = (b * (int)gridDim.y + blockIdx.y) * (int)gridDim.x + blockIdx.x;
#pragma unroll
    for (int i = 0; i < 4; i++) {
        float s = 0.f, s2 = 0.f;
        float* dst = g_raw + (size_t)(b * OC + oc0 + i) * HW + y0 * WW + x0 + lane;
#pragma unroll
        for (int j = 0; j < 4; j++) {
            float v0, v1;
            unpack2(acc[i][j], v0, v1);
            dst[(2 * j) * WW] = v0;
            dst[(2 * j + 1) * WW] = v1;
            s += v0 + v1;
            s2 += v0 * v0 + v1 * v1;
        }
#pragma unroll
        for (int off = 16; off > 0; off >>= 1) {
            s  += __shfl_down_sync(0xffffffffu, s, off);
            s2 += __shfl_down_sync(0xffffffffu, s2, off);
        }
        if (lane == 0) {
            g_part[0][oc0 + i][blk] = s;
            g_part[1][oc0 + i][blk] = s2;
        }
    }
}

// ---------------------------------------------------------------------------
// Reduce partials -> BN affine, folded with 1/2^NSTEPS.
// ---------------------------------------------------------------------------
__global__ __launch_bounds__(256) void stats_kernel(const float* __restrict__ gamma,
                                                    const float* __restrict__ beta) {
    __shared__ float sm[256], sm2[256];
    const int ch = blockIdx.x, tid = threadIdx.x;
    float s = 0.f, s2 = 0.f;
    for (int i = tid; i < 2048; i += 256) {
        s += g_part[0][ch][i];
        s2 += g_part[1][ch][i];
    }
    sm[tid] = s; sm2[tid] = s2;
    __syncthreads();
    for (int off = 128; off > 0; off >>= 1) {
        if (tid < off) { sm[tid] += sm[tid + off]; sm2[tid] += sm2[tid + off]; }
        __syncthreads();
    }
    if (tid == 0) {
        const float n = (float)(BS * HW);
        float mean = sm[0] / n;
        float var = sm2[0] / n - mean * mean;
        float r = rsqrtf(var + 1e-5f);
        const float scale = 1.0f / 128.0f;
        g_affa[ch] = gamma[ch] * r * scale;
        g_affb[ch] = (beta[ch] - gamma[ch] * mean * r) * scale;
    }
}

// ---------------------------------------------------------------------------
// One fused scaling-and-squaring step, two-phase block structure (R3 form:
// regs=32, occ ~87% — the measured-fastest variant).
// Block = 512 threads, tile = 32 consecutive pixels.
// Phase 1: thread (c, px) integrates flow channel c at pixel px, stores the
//          new flow (interleaved float2) and writes the warped-f sample m
//          into smem.
// Phase 2: thread (o, px) mixes the 16 smem m values with fuse weights and
//          RMWs the output plane (coalesced).
// FIRST step reads planar conv output + applies BN affine on every tap,
// and initializes out with fuse bias instead of RMW.
// LAST step skips the flow store (never read).
// ---------------------------------------------------------------------------
template <bool FIRST, bool LAST>
__global__ __launch_bounds__(512) void step_kernel(const float* __restrict__ f,
                                                   const float* __restrict__ fw,
                                                   const float* __restrict__ fbias,
                                                   float* __restrict__ out,
                                                   int step) {
    __shared__ float ws[256];        // [o][c]
    __shared__ float fb_s[16];
    __shared__ float sm_m[16][33];   // [c][px] padded

    const int tid = threadIdx.x;
    if (tid < 256) {
        int o = tid >> 4, c = tid & 15;
        ws[o * 16 + c] = fw[(o * 16 + c) * NSTEPS + step];
    }
    if (tid < 16) fb_s[tid] = fbias[tid];

    const int pix0 = blockIdx.x * 32;
    const int b  = pix0 >> 16;
    const int p0 = pix0 & 65535;

    // ---------------- phase 1: one (channel, pixel) per thread ----------------
    {
        const int c  = tid >> 5;
        const int pj = tid & 31;
        const int p  = p0 + pj;
        const int y  = p >> 8, x = p & 255;
        const float fy = (float)y, fx = (float)x;

        float dy, dx;
        const float* pdy = nullptr;
        const float* pdx = nullptr;
        const float2* pc = nullptr;
        float a0 = 0.f, b0 = 0.f, a1 = 0.f, b1 = 0.f;
        if (FIRST) {
            pdy = g_raw + (size_t)(b * OC + 2 * c) * HW;
            pdx = pdy + HW;
            a0 = g_affa[2 * c];     b0 = g_affb[2 * c];
            a1 = g_affa[2 * c + 1]; b1 = g_affb[2 * c + 1];
            dy = a0 * pdy[p] + b0;
            dx = a1 * pdx[p] + b1;
        } else {
            pc = ((step & 1) ? g_fA : g_fB) + (size_t)(b * IC + c) * HW;
            float2 cv = pc[p];
            dy = cv.x; dx = cv.y;
        }

        // warp(vec, vec): bilinear self-sample at (y+dy, x+dx), zero pad
        float py = fy + dy, px = fx + dx;
        float yf = floorf(py), xf = floorf(px);
        float wy1 = py - yf, wy0 = 1.f - wy1;
        float wx1 = px - xf, wx0 = 1.f - wx1;
        int yi = (int)yf, xi = (int)xf;
        float wdy = 0.f, wdx = 0.f;
#pragma unroll
        for (int t = 0; t < 4; t++) {
            int ty = yi + (t >> 1), tx = xi + (t & 1);
            float wgt = ((t >> 1) ? wy1 : wy0) * ((t & 1) ? wx1 : wx0);
            if ((unsigned)ty < (unsigned)HH && (unsigned)tx < (unsigned)WW) {
                if (FIRST) {
                    int ii = ty * WW + tx;
                    wdy += wgt * (a0 * pdy[ii] + b0);
                    wdx += wgt * (a1 * pdx[ii] + b1);
                } else {
                    float2 v = pc[ty * WW + tx];
                    wdy += wgt * v.x;
                    wdx += wgt * v.y;
                }
            }
        }
        float ndy = dy + wdy, ndx = dx + wdx;

        if (!LAST) {
            float2* vout = (FIRST ? g_fA : ((step & 1) ? g_fB : g_fA));
            float2 sv; sv.x = ndy; sv.y = ndx;
            vout[(size_t)(b * IC + c) * HW + p] = sv;
        }

        // warp(f[b,c], new flow): bilinear sample of f, zero pad
        const float* fp = f + (size_t)(b * IC + c) * HW;
        float qy = fy + ndy, qx = fx + ndx;
        float qyf = floorf(qy), qxf = floorf(qx);
        float vy1 = qy - qyf, vy0 = 1.f - vy1;
        float vx1 = qx - qxf, vx0 = 1.f - vx1;
        int qyi = (int)qyf, qxi = (int)qxf;
        float m = 0.f;
#pragma unroll
        for (int t = 0; t < 4; t++) {
            int ty = qyi + (t >> 1), tx = qxi + (t & 1);
            float wgt = ((t >> 1) ? vy1 : vy0) * ((t & 1) ? vx1 : vx0);
            if ((unsigned)ty < (unsigned)HH && (unsigned)tx < (unsigned)WW)
                m += wgt * fp[ty * WW + tx];
        }
        sm_m[c][pj] = m;
    }

    __syncthreads();

    // ---------------- phase 2: one (output, pixel) per thread ----------------
    {
        const int o  = tid >> 5;
        const int pj = tid & 31;
        const int p  = p0 + pj;
        float* op = out + (size_t)(b * IC + o) * HW + p;

        float acc = FIRST ? fb_s[o] : *op;
#pragma unroll
        for (int c = 0; c < 16; c++)
            acc += ws[o * 16 + c] * sm_m[c][pj];
        *op = acc;
    }
}

extern "C" void kernel_launch(void* const* d_in, const int* in_sizes, int n_in,
                              void* d_out, int out_size) {
    const float* f     = (const float*)d_in[0];
    const float* vw    = (const float*)d_in[1];
    const float* vb    = (const float*)d_in[2];
    const float* gamma = (const float*)d_in[3];
    const float* beta  = (const float*)d_in[4];
    const float* fw    = (const float*)d_in[5];
    const float* fbias = (const float*)d_in[6];
    float* out = (float*)d_out;

    dim3 cg(8, 32, 8);
    conv_kernel<<<cg, 256>>>(f, vw, vb);
    stats_kernel<<<32, 256>>>(gamma, beta);
    const int nblk = BS * HW / 32;   // 16384
    // step 0 writes g_fA; step s>=1: odd reads g_fA->writes g_fB, even reads g_fB->writes g_fA
    step_kernel<true, false><<<nblk, 512>>>(f, fw, fbias, out, 0);
    for (int s = 1; s < NSTEPS - 1; s++)
        step_kernel<false, false><<<nblk, 512>>>(f, fw, fbias, out, s);
    step_kernel<false, true><<<nblk, 512>>>(f, fw, fbias, out, NSTEPS - 1);
}